// round 5
// baseline (speedup 1.0000x reference)
#include <cuda_runtime.h>

#define N_NODES 50000
#define N_PAD   50048
#define N_EDGES 800000
#define HID     384
#define D_IN    256
#define N_LAYERS 6
#define NCLS    2
#define BN_EPS  1e-5f

// ---------------- scratch (no allocation allowed) ----------------
__device__ __align__(16) float g_bufA[(size_t)N_PAD * HID];
__device__ __align__(16) float g_bufB[(size_t)N_PAD * HID];
__device__ __align__(16) float g_bufC[(size_t)N_PAD * HID];
__device__ int   g_cnt[N_NODES];
__device__ int   g_ptr[N_NODES + 1];
__device__ int   g_cur[N_NODES];
__device__ int   g_esrc[N_EDGES];
__device__ float g_inv[N_NODES];
__device__ __align__(16) float g_stats[2 * HID];
__device__ __align__(16) float g_scsh[2 * HID];

// ---------------- small utility kernels ----------------
__global__ void k_zero_int(int* p, int n) {
    int i = blockIdx.x * blockDim.x + threadIdx.x;
    if (i < n) p[i] = 0;
}
__global__ void k_zero_f(float* p, int n) {
    int i = blockIdx.x * blockDim.x + threadIdx.x;
    if (i < n) p[i] = 0.f;
}
__global__ void k_hist(const int* __restrict__ col, int* __restrict__ cnt, int n) {
    int i = blockIdx.x * blockDim.x + threadIdx.x;
    if (i < n) atomicAdd(&cnt[col[i]], 1);
}
__global__ void k_inv(const int* __restrict__ cnt, float* __restrict__ inv, int n) {
    int i = blockIdx.x * blockDim.x + threadIdx.x;
    if (i < n) {
        int c = cnt[i];
        inv[i] = 1.f / (float)(c > 0 ? c : 1);
    }
}
__global__ void k_copy_int(const int* __restrict__ a, int* __restrict__ b, int n) {
    int i = blockIdx.x * blockDim.x + threadIdx.x;
    if (i < n) b[i] = a[i];
}

// single-block exclusive scan over N_NODES counts -> ptr, ptr[n] = total
__global__ void k_scan(const int* __restrict__ cnt, int* __restrict__ ptr, int n) {
    const int T = 1024;
    int t = threadIdx.x;
    int chunk = (n + T - 1) / T;
    int b = t * chunk; if (b > n) b = n;
    int e = b + chunk; if (e > n) e = n;
    int s = 0;
    for (int i = b; i < e; i++) s += cnt[i];
    __shared__ int sh[T];
    sh[t] = s;
    __syncthreads();
    for (int off = 1; off < T; off <<= 1) {
        int v = (t >= off) ? sh[t - off] : 0;
        __syncthreads();
        sh[t] += v;
        __syncthreads();
    }
    int run = sh[t] - s;  // exclusive prefix of this chunk
    for (int i = b; i < e; i++) { ptr[i] = run; run += cnt[i]; }
    if (t == T - 1) ptr[n] = sh[T - 1];
}

__global__ void k_fill(const int* __restrict__ row, const int* __restrict__ col,
                       int* __restrict__ cur, int* __restrict__ esrc, int n) {
    int i = blockIdx.x * blockDim.x + threadIdx.x;
    if (i < n) {
        int c = col[i];
        int pos = atomicAdd(&cur[c], 1);
        esrc[pos] = row[i];
    }
}

// ---------------- mean aggregation: one warp per node ----------------
__global__ void k_aggregate(const float* __restrict__ h, float* __restrict__ agg,
                            const int* __restrict__ ptr, const int* __restrict__ esrc,
                            const float* __restrict__ inv) {
    int w = (blockIdx.x * blockDim.x + threadIdx.x) >> 5;
    int lane = threadIdx.x & 31;
    if (w >= N_NODES) return;
    int b = ptr[w], e = ptr[w + 1];
    float4 a0 = make_float4(0.f, 0.f, 0.f, 0.f);
    float4 a1 = a0, a2 = a0;
    for (int j = b; j < e; j++) {
        const float4* hp = (const float4*)(h + (size_t)esrc[j] * HID);
        float4 v0 = hp[lane], v1 = hp[lane + 32], v2 = hp[lane + 64];
        a0.x += v0.x; a0.y += v0.y; a0.z += v0.z; a0.w += v0.w;
        a1.x += v1.x; a1.y += v1.y; a1.z += v1.z; a1.w += v1.w;
        a2.x += v2.x; a2.y += v2.y; a2.z += v2.z; a2.w += v2.w;
    }
    float iv = inv[w];
    a0.x *= iv; a0.y *= iv; a0.z *= iv; a0.w *= iv;
    a1.x *= iv; a1.y *= iv; a1.z *= iv; a1.w *= iv;
    a2.x *= iv; a2.y *= iv; a2.z *= iv; a2.w *= iv;
    float4* op = (float4*)(agg + (size_t)w * HID);
    op[lane] = a0; op[lane + 32] = a1; op[lane + 64] = a2;
}

// ---------------- SGEMM: C[M,N] (+)= A[M,K] @ B[K,N] + bias ----------------
// 128x128 block tile, BK=8, 256 threads, 8x8 per-thread, double-buffered smem.
// flags: 1 = accumulate into C, 2 = relu epilogue
__global__ void __launch_bounds__(256)
k_sgemm(const float* __restrict__ A, const float* __restrict__ B,
        const float* __restrict__ bias, float* __restrict__ C,
        int M, int N, int K, int flags) {
    __shared__ __align__(16) float As[2][8][128];
    __shared__ __align__(16) float Bs[2][8][128];
    const int t = threadIdx.x;
    const int bm = blockIdx.y * 128;
    const int bn = blockIdx.x * 128;
    const int tx = t & 15, ty = t >> 4;

    const int a_row = t >> 1;
    const int a_k   = (t & 1) << 2;
    const int b_row = t >> 5;
    const int b_col = (t & 31) << 2;

    float acc[8][8];
#pragma unroll
    for (int i = 0; i < 8; i++)
#pragma unroll
        for (int j = 0; j < 8; j++) acc[i][j] = 0.f;

    const int gr = bm + a_row;
    const int gc = bn + b_col;
    const bool aOk = (gr < M);
    const bool bOk = (gc < N);
    const float* Ap = A + (size_t)gr * K + a_k;
    const float* Bp = B + (size_t)b_row * N + gc;

    float4 aR = aOk ? *(const float4*)Ap : make_float4(0.f, 0.f, 0.f, 0.f);
    float4 bR = bOk ? *(const float4*)Bp : make_float4(0.f, 0.f, 0.f, 0.f);
    As[0][a_k + 0][a_row] = aR.x; As[0][a_k + 1][a_row] = aR.y;
    As[0][a_k + 2][a_row] = aR.z; As[0][a_k + 3][a_row] = aR.w;
    *(float4*)&Bs[0][b_row][b_col] = bR;
    __syncthreads();

    const int kTiles = K >> 3;
    int buf = 0;
    for (int kt = 0; kt < kTiles; kt++) {
        if (kt + 1 < kTiles) {
            aR = aOk ? *(const float4*)(Ap + (kt + 1) * 8)
                     : make_float4(0.f, 0.f, 0.f, 0.f);
            bR = bOk ? *(const float4*)(Bp + (size_t)(kt + 1) * 8 * N)
                     : make_float4(0.f, 0.f, 0.f, 0.f);
        }
#pragma unroll
        for (int kk = 0; kk < 8; kk++) {
            float a[8], b[8];
            *(float4*)&a[0] = *(const float4*)&As[buf][kk][ty * 8];
            *(float4*)&a[4] = *(const float4*)&As[buf][kk][ty * 8 + 4];
            *(float4*)&b[0] = *(const float4*)&Bs[buf][kk][tx * 8];
            *(float4*)&b[4] = *(const float4*)&Bs[buf][kk][tx * 8 + 4];
#pragma unroll
            for (int i = 0; i < 8; i++)
#pragma unroll
                for (int j = 0; j < 8; j++)
                    acc[i][j] = fmaf(a[i], b[j], acc[i][j]);
        }
        if (kt + 1 < kTiles) {
            buf ^= 1;
            As[buf][a_k + 0][a_row] = aR.x; As[buf][a_k + 1][a_row] = aR.y;
            As[buf][a_k + 2][a_row] = aR.z; As[buf][a_k + 3][a_row] = aR.w;
            *(float4*)&Bs[buf][b_row][b_col] = bR;
            __syncthreads();
        }
    }

    const bool do_acc  = (flags & 1) != 0;
    const bool do_relu = (flags & 2) != 0;
    float bb[8];
#pragma unroll
    for (int j = 0; j < 8; j++) {
        int c = bn + tx * 8 + j;
        bb[j] = (bias != nullptr && c < N) ? bias[c] : 0.f;
    }
#pragma unroll
    for (int i = 0; i < 8; i++) {
        int r = bm + ty * 8 + i;
        if (r >= M) continue;
        float* crow = C + (size_t)r * N + bn + tx * 8;
#pragma unroll
        for (int jj = 0; jj < 2; jj++) {
            int c = bn + tx * 8 + jj * 4;
            if (c >= N) continue;
            float4 v;
            v.x = acc[i][jj * 4 + 0] + bb[jj * 4 + 0];
            v.y = acc[i][jj * 4 + 1] + bb[jj * 4 + 1];
            v.z = acc[i][jj * 4 + 2] + bb[jj * 4 + 2];
            v.w = acc[i][jj * 4 + 3] + bb[jj * 4 + 3];
            if (do_acc) {
                float4 o = *(float4*)(crow + jj * 4);
                v.x += o.x; v.y += o.y; v.z += o.z; v.w += o.w;
            }
            if (do_relu) {
                v.x = fmaxf(v.x, 0.f); v.y = fmaxf(v.y, 0.f);
                v.z = fmaxf(v.z, 0.f); v.w = fmaxf(v.w, 0.f);
            }
            *(float4*)(crow + jj * 4) = v;
        }
    }
}

// ---------------- batchnorm ----------------
__global__ void k_bn_stats(const float* __restrict__ X, float* __restrict__ stats) {
    int c = threadIdx.x;                 // 384 threads, one column each
    int r0 = blockIdx.x * 250, r1 = r0 + 250;
    float s = 0.f, q = 0.f;
    for (int r = r0; r < r1; r++) {
        float v = X[(size_t)r * HID + c];
        s += v;
        q = fmaf(v, v, q);
    }
    atomicAdd(&stats[c], s);
    atomicAdd(&stats[HID + c], q);
}
__global__ void k_bn_finalize(const float* __restrict__ stats,
                              const float* __restrict__ g, const float* __restrict__ b,
                              float* __restrict__ scsh) {
    int c = threadIdx.x;
    float m   = stats[c] * (1.f / N_NODES);
    float var = stats[HID + c] * (1.f / N_NODES) - m * m;
    float sc  = g[c] * rsqrtf(var + BN_EPS);
    scsh[c] = sc;
    scsh[HID + c] = b[c] - m * sc;
}
__global__ void k_bn_apply(float* __restrict__ X, const float* __restrict__ scsh) {
    size_t i = ((size_t)blockIdx.x * blockDim.x + threadIdx.x) * 4;
    if (i >= (size_t)N_NODES * HID) return;
    int c = (int)(i % HID);
    float4 v  = *(float4*)(X + i);
    float4 sc = *(const float4*)(scsh + c);
    float4 sh = *(const float4*)(scsh + HID + c);
    v.x = fmaxf(fmaf(v.x, sc.x, sh.x), 0.f);
    v.y = fmaxf(fmaf(v.y, sc.y, sh.y), 0.f);
    v.z = fmaxf(fmaf(v.z, sc.z, sh.z), 0.f);
    v.w = fmaxf(fmaf(v.w, sc.w, sh.w), 0.f);
    *(float4*)(X + i) = v;
}

// ---------------- final logits: [N,96] @ [96,2] + b3 ----------------
__global__ void k_logits(const float* __restrict__ h2, const float* __restrict__ W3,
                         const float* __restrict__ b3, float* __restrict__ out) {
    int n = blockIdx.x * blockDim.x + threadIdx.x;
    if (n >= N_NODES) return;
    const float* r = h2 + (size_t)n * 96;
    float s0 = b3[0], s1 = b3[1];
#pragma unroll
    for (int k = 0; k < 96; k++) {
        float v = r[k];
        s0 = fmaf(v, W3[2 * k], s0);
        s1 = fmaf(v, W3[2 * k + 1], s1);
    }
    out[2 * n] = s0;
    out[2 * n + 1] = s1;
}

// ---------------- host ----------------
static void sgemm(const float* A, const float* B, const float* bias, float* C,
                  int M, int N, int K, int flags) {
    dim3 g((N + 127) / 128, (M + 127) / 128);
    k_sgemm<<<g, 256>>>(A, B, bias, C, M, N, K, flags);
}
static void bn_relu(float* X, const float* g, const float* b, float* stats, float* scsh) {
    k_zero_f<<<3, 256>>>(stats, 2 * HID);
    k_bn_stats<<<200, HID>>>(X, stats);
    k_bn_finalize<<<1, HID>>>(stats, g, b, scsh);
    k_bn_apply<<<18750, 256>>>(X, scsh);
}

extern "C" void kernel_launch(void* const* d_in, const int* in_sizes, int n_in,
                              void* d_out, int out_size) {
    const float* x    = (const float*)d_in[0];
    const int*   ei   = (const int*)d_in[1];
    const int*   row  = ei;
    const int*   col  = ei + N_EDGES;
    const float* W_in = (const float*)d_in[2];
    const float* b_in = (const float*)d_in[3];
    const float* bn0g = (const float*)d_in[4];
    const float* bn0b = (const float*)d_in[5];
    const float* Wl   = (const float*)d_in[6];
    const float* bl   = (const float*)d_in[7];
    const float* Wr   = (const float*)d_in[8];
    const float* bng  = (const float*)d_in[9];
    const float* bnb  = (const float*)d_in[10];
    const float* Wsk  = (const float*)d_in[11];
    const float* bsk  = (const float*)d_in[12];
    const float* W1   = (const float*)d_in[13];
    const float* b1   = (const float*)d_in[14];
    const float* W2   = (const float*)d_in[15];
    const float* b2   = (const float*)d_in[16];
    const float* W3   = (const float*)d_in[17];
    const float* b3   = (const float*)d_in[18];
    float* out = (float*)d_out;

    float *bufA, *bufB, *bufC, *inv, *stats, *scsh;
    int *cnt, *ptr, *cur, *esrc;
    cudaGetSymbolAddress((void**)&bufA, g_bufA);
    cudaGetSymbolAddress((void**)&bufB, g_bufB);
    cudaGetSymbolAddress((void**)&bufC, g_bufC);
    cudaGetSymbolAddress((void**)&cnt,  g_cnt);
    cudaGetSymbolAddress((void**)&ptr,  g_ptr);
    cudaGetSymbolAddress((void**)&cur,  g_cur);
    cudaGetSymbolAddress((void**)&esrc, g_esrc);
    cudaGetSymbolAddress((void**)&inv,  g_inv);
    cudaGetSymbolAddress((void**)&stats, g_stats);
    cudaGetSymbolAddress((void**)&scsh,  g_scsh);

    // ---- CSR by destination (built every launch; captured into graph) ----
    k_zero_int<<<(N_NODES + 255) / 256, 256>>>(cnt, N_NODES);
    k_hist<<<(N_EDGES + 255) / 256, 256>>>(col, cnt, N_EDGES);
    k_inv<<<(N_NODES + 255) / 256, 256>>>(cnt, inv, N_NODES);
    k_scan<<<1, 1024>>>(cnt, ptr, N_NODES);
    k_copy_int<<<(N_NODES + 255) / 256, 256>>>(ptr, cur, N_NODES);
    k_fill<<<(N_EDGES + 255) / 256, 256>>>(row, col, cur, esrc, N_EDGES);

    float* h   = bufA;
    float* agg = bufB;
    float* tmp = bufC;

    // ---- input projection + BN + relu ----
    sgemm(x, W_in, b_in, h, N_NODES, HID, D_IN, 0);
    bn_relu(h, bn0g, bn0b, stats, scsh);

    // ---- SAGE layers ----
    int skip = 0;
    for (int i = 0; i < N_LAYERS; i++) {
        k_aggregate<<<(N_NODES * 32 + 255) / 256, 256>>>(h, agg, ptr, esrc, inv);
        sgemm(agg, Wl + (size_t)i * HID * HID, bl + i * HID, tmp, N_NODES, HID, HID, 0);
        sgemm(h,   Wr + (size_t)i * HID * HID, nullptr,      tmp, N_NODES, HID, HID, 1);
        bn_relu(tmp, bng + i * HID, bnb + i * HID, stats, scsh);
        if ((i & 1) == 1) {  // skip after layers 2,4,6 (i=1,3,5)
            sgemm(h, Wsk + (size_t)skip * HID * HID, bsk + skip * HID, tmp,
                  N_NODES, HID, HID, 1);
            skip++;
        }
        float* t = h; h = tmp; tmp = t;
    }

    // embeddings go after the logits block in d_out
    cudaMemcpyAsync(out + (size_t)N_NODES * NCLS, h,
                    (size_t)N_NODES * HID * sizeof(float),
                    cudaMemcpyDeviceToDevice);

    // ---- MLP head ----
    float* h1 = agg;  // [N,192]
    float* h2 = tmp;  // [N,96]
    sgemm(h,  W1, b1, h1, N_NODES, HID / 2, HID, 2);
    sgemm(h1, W2, b2, h2, N_NODES, HID / 4, HID / 2, 2);
    k_logits<<<(N_NODES + 255) / 256, 256>>>(h2, W3, b3, out);
}